// round 10
// baseline (speedup 1.0000x reference)
#include <cuda_runtime.h>
#include <cuda_fp16.h>
#include <cstdint>

#define MAXN 8192
#define HD 64
#define SLOTS 32
#define EMB_MAX (50000 * HD)
#define BLKS 296
#define WPB 8
#define TW (BLKS * WPB)
#define GCH 128   // gather chunk rows

// ---------------- static device scratch ----------------
__device__ __half g_embh[EMB_MAX];
__device__ float g_h[MAXN * HD];
__device__ int g_wr[MAXN];
__device__ int g_cnt[MAXN];
__device__ int g_buck[MAXN * SLOTS];
__device__ int g_dep[MAXN];
__device__ volatile int g_depth[MAXN];
__device__ int g_hist[MAXN];
__device__ int g_off[MAXN];
__device__ int g_perm[MAXN];
__device__ volatile int g_ready[MAXN];
__device__ unsigned g_max[HD];
__device__ unsigned g_done;      // fused: last-block output election
__device__ unsigned g_done2;     // depth kernel: last-block scan election
__device__ volatile unsigned g_bar;  // fused: grid barrier after scatter

// ---------------- prep: fp16 embedding conversion + state reset ----------------
__global__ void prep_kernel(const float* __restrict__ emb, const int* __restrict__ tree,
                            int n_steps, int emb_total) {
    int t = blockIdx.x * blockDim.x + threadIdx.x;
    int e = t * 8;
    if (e + 7 < emb_total) {
        float4 f0 = *reinterpret_cast<const float4*>(emb + e);
        float4 f1 = *reinterpret_cast<const float4*>(emb + e + 4);
        *reinterpret_cast<__half2*>(g_embh + e)     = __floats2half2_rn(f0.x, f0.y);
        *reinterpret_cast<__half2*>(g_embh + e + 2) = __floats2half2_rn(f0.z, f0.w);
        *reinterpret_cast<__half2*>(g_embh + e + 4) = __floats2half2_rn(f1.x, f1.y);
        *reinterpret_cast<__half2*>(g_embh + e + 6) = __floats2half2_rn(f1.z, f1.w);
    }
    if (t < n_steps) {
        g_wr[t] = tree[2 * t + 1];
        g_ready[t] = 0;
    }
    if (t < MAXN) {
        g_cnt[t] = 0;
        g_hist[t] = 0;
        g_depth[t] = -1;
    }
    if (t < HD) g_max[t] = 0u;
    if (t == 0) { g_done = 0u; g_done2 = 0u; g_bar = 0u; }
}

// ---------------- bucket fill: writes per node ----------------
__global__ void fill_kernel(const int* __restrict__ tree, int n_steps) {
    int i = blockIdx.x * blockDim.x + threadIdx.x;
    if (i >= n_steps) return;
    int v = tree[2 * i + 1];
    int s = atomicAdd(&g_cnt[v], 1);
    if (s < SLOTS) g_buck[v * SLOTS + s] = i;
}

// ---------------- depth: dep(i), depth(i) by dataflow, histogram + prefix ----------------
__global__ void depth_kernel(const int* __restrict__ tree, int n_steps) {
    int i = blockIdx.x * blockDim.x + threadIdx.x;
    if (i < n_steps) {
        // dep(i): last j<i writing node tree[i,0]
        int v = tree[2 * i];
        int c = g_cnt[v];
        int d = -1;
        if (c <= SLOTS) {
            for (int s = 0; s < c; s++) {
                int j = g_buck[v * SLOTS + s];
                if (j < i && j > d) d = j;
            }
        } else {
            for (int j = i - 1; j >= 0; --j)
                if (g_wr[j] == v) { d = j; break; }
        }
        g_dep[i] = d;
        int mydepth = 0;
        if (d >= 0) {
            int dd;
            int cnt = 0;
            while ((dd = g_depth[d]) < 0)
                if (((++cnt) & 15) == 0) __nanosleep(64);
            mydepth = dd + 1;
        }
        g_depth[i] = mydepth;
        atomicAdd(&g_hist[mydepth], 1);
    }
    // last block computes exclusive prefix of g_hist into g_off
    __threadfence();
    __syncthreads();
    __shared__ bool amlast;
    if (threadIdx.x == 0)
        amlast = (atomicAdd(&g_done2, 1u) == gridDim.x - 1);
    __syncthreads();
    if (!amlast) return;
    __threadfence();   // acquire all hist writes
    __shared__ int partial[256];
    int t = threadIdx.x;
    int base = t * (MAXN / 256);
    int sum = 0;
    for (int k = 0; k < MAXN / 256; k++) sum += g_hist[base + k];
    partial[t] = sum;
    __syncthreads();
    // inclusive Hillis-Steele scan over 256 partials
    for (int off = 1; off < 256; off <<= 1) {
        int v2 = (t >= off) ? partial[t - off] : 0;
        __syncthreads();
        partial[t] += v2;
        __syncthreads();
    }
    int run = partial[t] - sum;   // exclusive base of this segment
    for (int k = 0; k < MAXN / 256; k++) {
        g_off[base + k] = run;
        run += g_hist[base + k];
    }
}

// ---------------- gather one 128-row chunk ----------------
__device__ __forceinline__ void gather_chunk(const float* __restrict__ xwr,
                                             const int* __restrict__ xir,
                                             int r0, int rl, int rg, float acc[8]) {
#pragma unroll 2
    for (int rr = 0; rr < GCH; rr += 16) {
        int rbase = r0 + rr + 4 * rg;
        float4 w4 = __ldg(reinterpret_cast<const float4*>(xwr + rbase));
        int4 i4 = __ldg(reinterpret_cast<const int4*>(xir + rbase));
        uint4 u0 = __ldg(reinterpret_cast<const uint4*>(g_embh + (size_t)i4.x * HD + rl * 8));
        uint4 u1 = __ldg(reinterpret_cast<const uint4*>(g_embh + (size_t)i4.y * HD + rl * 8));
        uint4 u2 = __ldg(reinterpret_cast<const uint4*>(g_embh + (size_t)i4.z * HD + rl * 8));
        uint4 u3 = __ldg(reinterpret_cast<const uint4*>(g_embh + (size_t)i4.w * HD + rl * 8));
#define ACCUM(U, W)                                                              \
        {                                                                        \
            float2 f0 = __half22float2(*reinterpret_cast<__half2*>(&U.x));      \
            float2 f1 = __half22float2(*reinterpret_cast<__half2*>(&U.y));      \
            float2 f2 = __half22float2(*reinterpret_cast<__half2*>(&U.z));      \
            float2 f3 = __half22float2(*reinterpret_cast<__half2*>(&U.w));      \
            acc[0] = fmaf(W, f0.x, acc[0]); acc[1] = fmaf(W, f0.y, acc[1]);     \
            acc[2] = fmaf(W, f1.x, acc[2]); acc[3] = fmaf(W, f1.y, acc[3]);     \
            acc[4] = fmaf(W, f2.x, acc[4]); acc[5] = fmaf(W, f2.y, acc[5]);     \
            acc[6] = fmaf(W, f3.x, acc[6]); acc[7] = fmaf(W, f3.y, acc[7]);     \
        }
        ACCUM(u0, w4.x) ACCUM(u1, w4.y) ACCUM(u2, w4.z) ACCUM(u3, w4.w)
#undef ACCUM
    }
}

// ---------------- fused: scatter + barrier + depth-ordered gather/GRU dataflow ----------------
__global__ void __launch_bounds__(256, 2)
fused_kernel(const float* __restrict__ xw, const int* __restrict__ xi,
             const float* __restrict__ Wz, const float* __restrict__ Uz,
             const float* __restrict__ bz,
             const float* __restrict__ Wr, const float* __restrict__ Ur,
             const float* __restrict__ br,
             const float* __restrict__ Wh, const float* __restrict__ Uh,
             const float* __restrict__ bh,
             const int* __restrict__ np_ptr, int L, int n_steps,
             float* __restrict__ out) {
    extern __shared__ float sm[];
    float* sWzr = sm;             // [k*128 + 4l + {Wz2l,Wz2l+1,Wr2l,Wr2l+1}]
    float* sWh2 = sm + 8192;
    float* sUzr = sm + 12288;
    float* sUh2 = sm + 20480;
    float* sXe = sm + 24576;      // per-warp 64
    float* sP  = sm + 25088;
    float* sPr = sm + 25600;

    int tid = threadIdx.x;
    int wid = tid >> 5, l = tid & 31;
    int rl = l & 7, rg = l >> 3;

    // ---- scatter: perm[level-major order] = step index ----
    int gtid = blockIdx.x * 256 + tid;
    if (gtid < n_steps) {
        int pos = atomicAdd(&g_off[g_depth[gtid]], 1);
        g_perm[pos] = gtid;
    }

    // ---- weight packing overlaps other blocks' scatter ----
    for (int t = tid; t < 8192; t += 256) {
        int k = t >> 7, q = t & 127, lane = q >> 2, c = q & 3;
        int j = 2 * lane + (c & 1);
        sWzr[t] = (c < 2 ? Wz : Wr)[j * 64 + k];
        sUzr[t] = (c < 2 ? Uz : Ur)[j * 64 + k];
    }
    for (int t = tid; t < 4096; t += 256) {
        int kp = t >> 7, q = t & 127, lane = q >> 2, c = q & 3;
        int j = 2 * lane + (c & 1);
        int k = 2 * kp + (c >> 1);
        sWh2[t] = Wh[j * 64 + k];
        sUh2[t] = Uh[j * 64 + k];
    }
    float2 bz2 = reinterpret_cast<const float2*>(bz)[l];
    float2 br2 = reinterpret_cast<const float2*>(br)[l];
    float2 bh2 = reinterpret_cast<const float2*>(bh)[l];
    int np1 = np_ptr[0] - 1;

    // ---- software grid barrier (all 296 blocks resident) ----
    __threadfence();              // release scatter writes
    __syncthreads();
    if (tid == 0) {
        atomicAdd((unsigned*)&g_bar, 1u);
        int cnt = 0;
        while (g_bar < (unsigned)gridDim.x)
            if (((++cnt) & 15) == 0) __nanosleep(128);
    }
    __syncthreads();
    __threadfence();              // acquire perm

    const float4* Wzr4 = reinterpret_cast<const float4*>(sWzr);
    const float4* Wh4  = reinterpret_cast<const float4*>(sWh2);
    const float4* Uzr4 = reinterpret_cast<const float4*>(sUzr);
    const float4* Uh4  = reinterpret_cast<const float4*>(sUh2);
    float* xe_w = sXe + wid * 64;
    float* p_w  = sP + wid * 64;
    float* pr_w = sPr + wid * 64;
    float2 lm = make_float2(-3.402823466e38f, -3.402823466e38f);

    // preamble: gather first owned slot
    int slot0 = blockIdx.x * WPB + wid;
    float acc[8] = {0.f, 0.f, 0.f, 0.f, 0.f, 0.f, 0.f, 0.f};
    int i_cur = -1;
    if (slot0 < n_steps) {
        i_cur = __ldg(&g_perm[slot0]);
        const float* xwr = xw + (size_t)i_cur * L;
        const int* xir = xi + (size_t)i_cur * L;
        for (int r0 = 0; r0 < L; r0 += GCH) gather_chunk(xwr, xir, r0, rl, rg, acc);
    }

    for (int slot = slot0; slot < n_steps; slot += TW) {
        int i = i_cur;
        int snext = slot + TW;
        bool has_next = (snext < n_steps);
        int i_next = has_next ? __ldg(&g_perm[snext]) : 0;
        const float* xwrN = xw + (size_t)i_next * L;
        const int* xirN = xi + (size_t)i_next * L;
        i_cur = i_next;

        // ---- reduce acc -> xe_w (sum over rg groups) ----
#pragma unroll
        for (int u = 0; u < 8; u++) {
            acc[u] += __shfl_xor_sync(0xffffffffu, acc[u], 8);
            acc[u] += __shfl_xor_sync(0xffffffffu, acc[u], 16);
        }
        if (rg == 0) {
#pragma unroll
            for (int u = 0; u < 8; u++) xe_w[rl * 8 + u] = acc[u];
        }
        __syncwarp();
#pragma unroll
        for (int u = 0; u < 8; u++) acc[u] = 0.f;

        int d = __ldg(&g_dep[i]);

        // ---- W matvecs (pre-wait): a = W xe + b ----
        float4 wzrA = make_float4(bz2.x, bz2.y, br2.x, br2.y);
        float4 wzrB = make_float4(0.f, 0.f, 0.f, 0.f);
        float2 whA = bh2, whB = make_float2(0.f, 0.f);
#pragma unroll
        for (int k = 0; k < 64; k += 2) {
            float2 x = *reinterpret_cast<const float2*>(&xe_w[k]);
            float4 m0 = Wzr4[k * 32 + l];
            float4 m1 = Wzr4[(k + 1) * 32 + l];
            wzrA.x = fmaf(m0.x, x.x, wzrA.x); wzrA.y = fmaf(m0.y, x.x, wzrA.y);
            wzrA.z = fmaf(m0.z, x.x, wzrA.z); wzrA.w = fmaf(m0.w, x.x, wzrA.w);
            wzrB.x = fmaf(m1.x, x.y, wzrB.x); wzrB.y = fmaf(m1.y, x.y, wzrB.y);
            wzrB.z = fmaf(m1.z, x.y, wzrB.z); wzrB.w = fmaf(m1.w, x.y, wzrB.w);
            float4 mh = Wh4[(k >> 1) * 32 + l];
            whA.x = fmaf(mh.x, x.x, whA.x); whA.y = fmaf(mh.y, x.x, whA.y);
            whB.x = fmaf(mh.z, x.y, whB.x); whB.y = fmaf(mh.w, x.y, whB.y);
        }
        float2 az2 = make_float2(wzrA.x + wzrB.x, wzrA.y + wzrB.y);
        float2 ar2 = make_float2(wzrA.z + wzrB.z, wzrA.w + wzrB.w);
        float2 ah2 = make_float2(whA.x + whB.x, whA.y + whB.y);

        // ---- probe dep (usually ready: dep has lower level); prefetch while not ----
        int pr_r0 = 0;
        float2 p2;
        if (d >= 0) {
            int rdy = (l == 0) ? g_ready[d] : 0;
            rdy = __shfl_sync(0xffffffffu, rdy, 0);
            while (!rdy) {
                if (has_next && pr_r0 < L) {
                    gather_chunk(xwrN, xirN, pr_r0, rl, rg, acc);
                    pr_r0 += GCH;
                } else {
                    if (l == 0) {
                        int cnt = 0;
                        while (g_ready[d] == 0)
                            if (((++cnt) & 31) == 0) __nanosleep(64);
                    }
                    break;
                }
                rdy = (l == 0) ? g_ready[d] : 0;
                rdy = __shfl_sync(0xffffffffu, rdy, 0);
            }
            __syncwarp();
            __threadfence();   // acquire: order p load after flag observation
            p2 = __ldcg(reinterpret_cast<const float2*>(g_h + (size_t)d * HD) + l);
        } else {
            p2 = make_float2(0.f, 0.f);
        }
        *reinterpret_cast<float2*>(&p_w[2 * l]) = p2;
        __syncwarp();

        // ---- U z/r matvec ----
        float4 sA = make_float4(az2.x, az2.y, ar2.x, ar2.y);
        float4 sB = make_float4(0.f, 0.f, 0.f, 0.f);
#pragma unroll
        for (int k = 0; k < 64; k += 2) {
            float2 x = *reinterpret_cast<const float2*>(&p_w[k]);
            float4 m0 = Uzr4[k * 32 + l];
            float4 m1 = Uzr4[(k + 1) * 32 + l];
            sA.x = fmaf(m0.x, x.x, sA.x); sA.y = fmaf(m0.y, x.x, sA.y);
            sA.z = fmaf(m0.z, x.x, sA.z); sA.w = fmaf(m0.w, x.x, sA.w);
            sB.x = fmaf(m1.x, x.y, sB.x); sB.y = fmaf(m1.y, x.y, sB.y);
            sB.z = fmaf(m1.z, x.y, sB.z); sB.w = fmaf(m1.w, x.y, sB.w);
        }
        float2 z2, r2;
        z2.x = fminf(fmaxf(0.2f * (sA.x + sB.x) + 0.5f, 0.f), 1.f);
        z2.y = fminf(fmaxf(0.2f * (sA.y + sB.y) + 0.5f, 0.f), 1.f);
        r2.x = fminf(fmaxf(0.2f * (sA.z + sB.z) + 0.5f, 0.f), 1.f);
        r2.y = fminf(fmaxf(0.2f * (sA.w + sB.w) + 0.5f, 0.f), 1.f);
        *reinterpret_cast<float2*>(&pr_w[2 * l]) =
            make_float2(p2.x * r2.x, p2.y * r2.y);
        __syncwarp();

        // ---- Uh matvec ----
        float2 hA = ah2, hB = make_float2(0.f, 0.f);
#pragma unroll
        for (int kp = 0; kp < 32; kp++) {
            float2 x = *reinterpret_cast<const float2*>(&pr_w[2 * kp]);
            float4 m = Uh4[kp * 32 + l];
            hA.x = fmaf(m.x, x.x, hA.x); hA.y = fmaf(m.y, x.x, hA.y);
            hB.x = fmaf(m.z, x.y, hB.x); hB.y = fmaf(m.w, x.y, hB.y);
        }
        float2 h2;
        h2.x = z2.x * p2.x + (1.f - z2.x) * tanhf(hA.x + hB.x);
        h2.y = z2.y * p2.y + (1.f - z2.y) * tanhf(hA.y + hB.y);

        __stcg(reinterpret_cast<float2*>(g_h + (size_t)i * HD) + l, h2);
        if (i >= np1) {
            lm.x = fmaxf(lm.x, h2.x);
            lm.y = fmaxf(lm.y, h2.y);
        }
        __threadfence();          // release h stores
        __syncwarp();
        if (l == 0) g_ready[i] = 1;

        // ---- finish remaining gather chunks for next slot's step ----
        while (has_next && pr_r0 < L) {
            gather_chunk(xwrN, xirN, pr_r0, rl, rg, acc);
            pr_r0 += GCH;
        }
    }

    // fold local max, then last block writes output
    unsigned ux = __float_as_uint(lm.x);
    ux = (ux & 0x80000000u) ? ~ux : (ux | 0x80000000u);
    unsigned uy = __float_as_uint(lm.y);
    uy = (uy & 0x80000000u) ? ~uy : (uy | 0x80000000u);
    atomicMax(&g_max[2 * l], ux);
    atomicMax(&g_max[2 * l + 1], uy);
    __threadfence();
    __syncthreads();
    __shared__ unsigned s_last;
    if (tid == 0) s_last = (atomicAdd(&g_done, 1u) == BLKS - 1) ? 1u : 0u;
    __syncthreads();
    if (s_last && tid < HD) {
        unsigned u = atomicMax(&g_max[tid], 0u);   // atomic read of final value
        unsigned b = (u & 0x80000000u) ? (u & 0x7fffffffu) : ~u;
        out[tid] = __uint_as_float(b);
    }
}

// ---------------- launch ----------------
extern "C" void kernel_launch(void* const* d_in, const int* in_sizes, int n_in,
                              void* d_out, int out_size) {
    const float* xw = (const float*)d_in[0];
    const int* xi = (const int*)d_in[1];
    const int* tree = (const int*)d_in[2];
    const int* np = (const int*)d_in[3];
    const float* emb = (const float*)d_in[4];
    const float* Wz = (const float*)d_in[5];
    const float* Uz = (const float*)d_in[6];
    const float* bz = (const float*)d_in[7];
    const float* Wr = (const float*)d_in[8];
    const float* Ur = (const float*)d_in[9];
    const float* br = (const float*)d_in[10];
    const float* Wh = (const float*)d_in[11];
    const float* Uh = (const float*)d_in[12];
    const float* bh = (const float*)d_in[13];

    int N = in_sizes[2] / 2;      // tree is [N,2]
    int L = in_sizes[0] / N;      // x_word is [N,L]
    int n_steps = N - 1;
    int emb_total = in_sizes[4];  // V*H floats

    static int smem_set = 0;
    const int SMEM_BYTES = (24576 + 1536) * 4;  // 104448
    if (!smem_set) {
        cudaFuncSetAttribute(fused_kernel,
                             cudaFuncAttributeMaxDynamicSharedMemorySize, SMEM_BYTES);
        smem_set = 1;
    }

    int prep_threads = (emb_total + 7) / 8;
    if (prep_threads < MAXN) prep_threads = MAXN;
    prep_kernel<<<(prep_threads + 255) / 256, 256>>>(emb, tree, n_steps, emb_total);
    fill_kernel<<<(n_steps + 255) / 256, 256>>>(tree, n_steps);
    depth_kernel<<<(n_steps + 255) / 256, 256>>>(tree, n_steps);
    fused_kernel<<<BLKS, 256, SMEM_BYTES>>>(xw, xi, Wz, Uz, bz, Wr, Ur, br,
                                            Wh, Uh, bh, np, L, n_steps,
                                            (float*)d_out);
}

// round 11
// speedup vs baseline: 1.3095x; 1.3095x over previous
#include <cuda_runtime.h>
#include <cuda_fp16.h>
#include <cstdint>

#define MAXN 8192
#define HD 64
#define SLOTS 32
#define EMB_MAX (50000 * HD)
#define BLKS 296
#define WPB 8
#define TW (BLKS * WPB)
#define GCH 128   // direct-LDG prefetch chunk rows (wait-loop path)

// ---------------- static device scratch ----------------
__device__ __half g_embh[EMB_MAX];
__device__ float g_h[MAXN * HD];
__device__ int g_wr[MAXN];
__device__ int g_cnt[MAXN];
__device__ int g_buck[MAXN * SLOTS];
__device__ volatile int g_ready[MAXN];
__device__ unsigned g_max[HD];
__device__ unsigned g_done;

// ---------------- prep: fp16 embedding conversion + state reset ----------------
__global__ void prep_kernel(const float* __restrict__ emb, const int* __restrict__ tree,
                            int n_steps, int emb_total) {
    int t = blockIdx.x * blockDim.x + threadIdx.x;
    int e = t * 8;
    if (e + 7 < emb_total) {
        float4 f0 = *reinterpret_cast<const float4*>(emb + e);
        float4 f1 = *reinterpret_cast<const float4*>(emb + e + 4);
        *reinterpret_cast<__half2*>(g_embh + e)     = __floats2half2_rn(f0.x, f0.y);
        *reinterpret_cast<__half2*>(g_embh + e + 2) = __floats2half2_rn(f0.z, f0.w);
        *reinterpret_cast<__half2*>(g_embh + e + 4) = __floats2half2_rn(f1.x, f1.y);
        *reinterpret_cast<__half2*>(g_embh + e + 6) = __floats2half2_rn(f1.z, f1.w);
    }
    if (t < n_steps) {
        g_wr[t] = tree[2 * t + 1];
        g_ready[t] = 0;
    }
    if (t < MAXN) g_cnt[t] = 0;
    if (t < HD) g_max[t] = 0u;
    if (t == 0) g_done = 0u;
}

// ---------------- bucket fill: writes per node ----------------
__global__ void fill_kernel(const int* __restrict__ tree, int n_steps) {
    int i = blockIdx.x * blockDim.x + threadIdx.x;
    if (i >= n_steps) return;
    int v = tree[2 * i + 1];
    int s = atomicAdd(&g_cnt[v], 1);
    if (s < SLOTS) g_buck[v * SLOTS + s] = i;
}

// ---------------- emb accumulate (shared by both gather paths) ----------------
#define ACCUM(U, W)                                                              \
        {                                                                        \
            float2 f0 = __half22float2(*reinterpret_cast<__half2*>(&U.x));      \
            float2 f1 = __half22float2(*reinterpret_cast<__half2*>(&U.y));      \
            float2 f2 = __half22float2(*reinterpret_cast<__half2*>(&U.z));      \
            float2 f3 = __half22float2(*reinterpret_cast<__half2*>(&U.w));      \
            acc[0] = fmaf(W, f0.x, acc[0]); acc[1] = fmaf(W, f0.y, acc[1]);     \
            acc[2] = fmaf(W, f1.x, acc[2]); acc[3] = fmaf(W, f1.y, acc[3]);     \
            acc[4] = fmaf(W, f2.x, acc[4]); acc[5] = fmaf(W, f2.y, acc[5]);     \
            acc[6] = fmaf(W, f3.x, acc[6]); acc[7] = fmaf(W, f3.y, acc[7]);     \
        }

// ---------------- direct-LDG gather chunk (wait-loop opportunistic path) ----------------
__device__ __forceinline__ void gather_chunk(const float* __restrict__ xwr,
                                             const int* __restrict__ xir,
                                             int r0, int rl, int rg, float acc[8]) {
#pragma unroll 2
    for (int rr = 0; rr < GCH; rr += 16) {
        int rbase = r0 + rr + 4 * rg;
        float4 w4 = __ldg(reinterpret_cast<const float4*>(xwr + rbase));
        int4 i4 = __ldg(reinterpret_cast<const int4*>(xir + rbase));
        uint4 u0 = __ldg(reinterpret_cast<const uint4*>(g_embh + (size_t)i4.x * HD + rl * 8));
        uint4 u1 = __ldg(reinterpret_cast<const uint4*>(g_embh + (size_t)i4.y * HD + rl * 8));
        uint4 u2 = __ldg(reinterpret_cast<const uint4*>(g_embh + (size_t)i4.z * HD + rl * 8));
        uint4 u3 = __ldg(reinterpret_cast<const uint4*>(g_embh + (size_t)i4.w * HD + rl * 8));
        ACCUM(u0, w4.x) ACCUM(u1, w4.y) ACCUM(u2, w4.z) ACCUM(u3, w4.w)
    }
}

// ---------------- cp.async: stage one 64-row half of xw/xi into smem ----------------
__device__ __forceinline__ void issue_half(const float* __restrict__ xwr,
                                           const int* __restrict__ xir,
                                           int row0, uint32_t xw_s, uint32_t xi_s, int l) {
    const float* gw = xwr + row0 + 2 * l;   // lane copies rows 2l, 2l+1 (8B)
    const int*   gi = xir + row0 + 2 * l;
    uint32_t dw = xw_s + 8u * l;
    uint32_t di = xi_s + 8u * l;
    asm volatile("cp.async.ca.shared.global [%0], [%1], 8;" :: "r"(dw), "l"(gw));
    asm volatile("cp.async.ca.shared.global [%0], [%1], 8;" :: "r"(di), "l"(gi));
    asm volatile("cp.async.commit_group;" ::: "memory");
}

// ---------------- pipelined gather over [r0, L): cp.async-staged indices ----------------
// xwS/xiS: per-warp double buffers of 64 floats/ints each (xwS[buf*64], xiS[buf*64]).
__device__ __forceinline__ void gather_pipelined(const float* __restrict__ xwr,
                                                 const int* __restrict__ xir,
                                                 int r0, int L,
                                                 float* xwS, int* xiS,
                                                 uint32_t xwS_a, uint32_t xiS_a,
                                                 int rl, int rg, int l, float acc[8]) {
    int H = (L - r0) >> 6;           // number of 64-row halves
    if (H <= 0) return;
    issue_half(xwr, xir, r0, xwS_a, xiS_a, l);
    if (H > 1) issue_half(xwr, xir, r0 + 64, xwS_a + 256u, xiS_a + 256u, l);
    for (int h = 0; h < H; h++) {
        if (h < H - 1) asm volatile("cp.async.wait_group 1;" ::: "memory");
        else           asm volatile("cp.async.wait_group 0;" ::: "memory");
        __syncwarp();
        int b = h & 1;
        if (h + 2 < H)
            issue_half(xwr, xir, r0 + (h + 2) * 64,
                       xwS_a + (b ? 256u : 0u), xiS_a + (b ? 256u : 0u), l);
        float* sw = xwS + b * 64;
        int* si = xiS + b * 64;
#pragma unroll
        for (int rr = 0; rr < 64; rr += 16) {
            int rb = rr + 4 * rg;
            float4 w4 = *reinterpret_cast<const float4*>(sw + rb);
            int4 i4 = *reinterpret_cast<const int4*>(si + rb);
            uint4 u0 = __ldg(reinterpret_cast<const uint4*>(g_embh + (size_t)i4.x * HD + rl * 8));
            uint4 u1 = __ldg(reinterpret_cast<const uint4*>(g_embh + (size_t)i4.y * HD + rl * 8));
            uint4 u2 = __ldg(reinterpret_cast<const uint4*>(g_embh + (size_t)i4.z * HD + rl * 8));
            uint4 u3 = __ldg(reinterpret_cast<const uint4*>(g_embh + (size_t)i4.w * HD + rl * 8));
            ACCUM(u0, w4.x) ACCUM(u1, w4.y) ACCUM(u2, w4.z) ACCUM(u3, w4.w)
        }
        __syncwarp();   // all lanes done reading buf b before it is overwritten
    }
}

// ---------------- fused gather + GRU dataflow (one step per warp, pipelined) ----------------
__global__ void __launch_bounds__(256, 2)
fused_kernel(const float* __restrict__ xw, const int* __restrict__ xi,
             const int* __restrict__ tree,
             const float* __restrict__ Wz, const float* __restrict__ Uz,
             const float* __restrict__ bz,
             const float* __restrict__ Wr, const float* __restrict__ Ur,
             const float* __restrict__ br,
             const float* __restrict__ Wh, const float* __restrict__ Uh,
             const float* __restrict__ bh,
             const int* __restrict__ np_ptr, int L, int n_steps,
             float* __restrict__ out) {
    extern __shared__ float sm[];
    float* sWzr = sm;             // [k*128 + 4l + {Wz2l,Wz2l+1,Wr2l,Wr2l+1}]
    float* sWh2 = sm + 8192;
    float* sUzr = sm + 12288;
    float* sUh2 = sm + 20480;
    float* sXe = sm + 24576;      // per-warp 64
    float* sP  = sm + 25088;
    float* sPr = sm + 25600;
    float* sXW = sm + 26112;      // per-warp 2x64 floats (cp.async staging)
    int*   sXI = reinterpret_cast<int*>(sm + 27136);  // per-warp 2x64 ints

    int tid = threadIdx.x;
    int wid = tid >> 5, l = tid & 31;
    int rl = l & 7, rg = l >> 3;

    // pack weight matrices into interleaved smem layouts
    for (int t = tid; t < 8192; t += 256) {
        int k = t >> 7, q = t & 127, lane = q >> 2, c = q & 3;
        int j = 2 * lane + (c & 1);
        sWzr[t] = (c < 2 ? Wz : Wr)[j * 64 + k];
        sUzr[t] = (c < 2 ? Uz : Ur)[j * 64 + k];
    }
    for (int t = tid; t < 4096; t += 256) {
        int kp = t >> 7, q = t & 127, lane = q >> 2, c = q & 3;
        int j = 2 * lane + (c & 1);
        int k = 2 * kp + (c >> 1);
        sWh2[t] = Wh[j * 64 + k];
        sUh2[t] = Uh[j * 64 + k];
    }
    float2 bz2 = reinterpret_cast<const float2*>(bz)[l];
    float2 br2 = reinterpret_cast<const float2*>(br)[l];
    float2 bh2 = reinterpret_cast<const float2*>(bh)[l];
    int np1 = np_ptr[0] - 1;
    __syncthreads();

    const float4* Wzr4 = reinterpret_cast<const float4*>(sWzr);
    const float4* Wh4  = reinterpret_cast<const float4*>(sWh2);
    const float4* Uzr4 = reinterpret_cast<const float4*>(sUzr);
    const float4* Uh4  = reinterpret_cast<const float4*>(sUh2);
    float* xe_w = sXe + wid * 64;
    float* p_w  = sP + wid * 64;
    float* pr_w = sPr + wid * 64;
    float* xwS = sXW + wid * 128;
    int*   xiS = sXI + wid * 128;
    uint32_t xwS_a = (uint32_t)__cvta_generic_to_shared(xwS);
    uint32_t xiS_a = (uint32_t)__cvta_generic_to_shared(xiS);
    float2 lm = make_float2(-3.402823466e38f, -3.402823466e38f);

    // preamble: gather first owned step (pipelined)
    int i0 = blockIdx.x * WPB + wid;
    float acc[8] = {0.f, 0.f, 0.f, 0.f, 0.f, 0.f, 0.f, 0.f};
    if (i0 < n_steps) {
        gather_pipelined(xw + (size_t)i0 * L, xi + (size_t)i0 * L, 0, L,
                         xwS, xiS, xwS_a, xiS_a, rl, rg, l, acc);
    }

    for (int i = i0; i < n_steps; i += TW) {
        int inext = i + TW;
        bool has_next = (inext < n_steps);
        const float* xwrN = xw + (size_t)inext * L;
        const int* xirN = xi + (size_t)inext * L;

        // ---- reduce acc -> xe_w (sum over rg groups) ----
#pragma unroll
        for (int u = 0; u < 8; u++) {
            acc[u] += __shfl_xor_sync(0xffffffffu, acc[u], 8);
            acc[u] += __shfl_xor_sync(0xffffffffu, acc[u], 16);
        }
        if (rg == 0) {
#pragma unroll
            for (int u = 0; u < 8; u++) xe_w[rl * 8 + u] = acc[u];
        }
        __syncwarp();
#pragma unroll
        for (int u = 0; u < 8; u++) acc[u] = 0.f;

        // ---- dep(i): last j<i writing node tree[i,0] ----
        int v = tree[2 * i];
        int c = g_cnt[v];
        int d = -1;
        if (c <= SLOTS) {
            if (l < c) {
                int j = g_buck[v * SLOTS + l];
                if (j < i) d = j;
            }
        } else {
            if (l == 0)
                for (int j = i - 1; j >= 0; --j)
                    if (g_wr[j] == v) { d = j; break; }
        }
        d = __reduce_max_sync(0xffffffffu, d);

        // ---- W matvecs (pre-wait): a = W xe + b ----
        float4 wzrA = make_float4(bz2.x, bz2.y, br2.x, br2.y);
        float4 wzrB = make_float4(0.f, 0.f, 0.f, 0.f);
        float2 whA = bh2, whB = make_float2(0.f, 0.f);
#pragma unroll
        for (int k = 0; k < 64; k += 2) {
            float2 x = *reinterpret_cast<const float2*>(&xe_w[k]);
            float4 m0 = Wzr4[k * 32 + l];
            float4 m1 = Wzr4[(k + 1) * 32 + l];
            wzrA.x = fmaf(m0.x, x.x, wzrA.x); wzrA.y = fmaf(m0.y, x.x, wzrA.y);
            wzrA.z = fmaf(m0.z, x.x, wzrA.z); wzrA.w = fmaf(m0.w, x.x, wzrA.w);
            wzrB.x = fmaf(m1.x, x.y, wzrB.x); wzrB.y = fmaf(m1.y, x.y, wzrB.y);
            wzrB.z = fmaf(m1.z, x.y, wzrB.z); wzrB.w = fmaf(m1.w, x.y, wzrB.w);
            float4 mh = Wh4[(k >> 1) * 32 + l];
            whA.x = fmaf(mh.x, x.x, whA.x); whA.y = fmaf(mh.y, x.x, whA.y);
            whB.x = fmaf(mh.z, x.y, whB.x); whB.y = fmaf(mh.w, x.y, whB.y);
        }
        float2 az2 = make_float2(wzrA.x + wzrB.x, wzrA.y + wzrB.y);
        float2 ar2 = make_float2(wzrA.z + wzrB.z, wzrA.w + wzrB.w);
        float2 ah2 = make_float2(whA.x + whB.x, whA.y + whB.y);

        // ---- probe dep; gather next step's chunks (direct LDG) while not ready ----
        int pr_r0 = 0;
        float2 p2;
        if (d >= 0) {
            int rdy = (l == 0) ? g_ready[d] : 0;
            rdy = __shfl_sync(0xffffffffu, rdy, 0);
            while (!rdy) {
                if (has_next && pr_r0 < L) {
                    gather_chunk(xwrN, xirN, pr_r0, rl, rg, acc);
                    pr_r0 += GCH;
                } else {
                    if (l == 0) {
                        int cnt = 0;
                        while (g_ready[d] == 0)
                            if (((++cnt) & 31) == 0) __nanosleep(64);
                    }
                    break;
                }
                rdy = (l == 0) ? g_ready[d] : 0;
                rdy = __shfl_sync(0xffffffffu, rdy, 0);
            }
            __syncwarp();
            __threadfence();   // acquire: order p load after flag observation
            p2 = __ldcg(reinterpret_cast<const float2*>(g_h + (size_t)d * HD) + l);
        } else {
            p2 = make_float2(0.f, 0.f);
        }
        *reinterpret_cast<float2*>(&p_w[2 * l]) = p2;
        __syncwarp();

        // ---- U z/r matvec ----
        float4 sA = make_float4(az2.x, az2.y, ar2.x, ar2.y);
        float4 sB = make_float4(0.f, 0.f, 0.f, 0.f);
#pragma unroll
        for (int k = 0; k < 64; k += 2) {
            float2 x = *reinterpret_cast<const float2*>(&p_w[k]);
            float4 m0 = Uzr4[k * 32 + l];
            float4 m1 = Uzr4[(k + 1) * 32 + l];
            sA.x = fmaf(m0.x, x.x, sA.x); sA.y = fmaf(m0.y, x.x, sA.y);
            sA.z = fmaf(m0.z, x.x, sA.z); sA.w = fmaf(m0.w, x.x, sA.w);
            sB.x = fmaf(m1.x, x.y, sB.x); sB.y = fmaf(m1.y, x.y, sB.y);
            sB.z = fmaf(m1.z, x.y, sB.z); sB.w = fmaf(m1.w, x.y, sB.w);
        }
        float2 z2, r2;
        z2.x = fminf(fmaxf(0.2f * (sA.x + sB.x) + 0.5f, 0.f), 1.f);
        z2.y = fminf(fmaxf(0.2f * (sA.y + sB.y) + 0.5f, 0.f), 1.f);
        r2.x = fminf(fmaxf(0.2f * (sA.z + sB.z) + 0.5f, 0.f), 1.f);
        r2.y = fminf(fmaxf(0.2f * (sA.w + sB.w) + 0.5f, 0.f), 1.f);
        *reinterpret_cast<float2*>(&pr_w[2 * l]) =
            make_float2(p2.x * r2.x, p2.y * r2.y);
        __syncwarp();

        // ---- Uh matvec ----
        float2 hA = ah2, hB = make_float2(0.f, 0.f);
#pragma unroll
        for (int kp = 0; kp < 32; kp++) {
            float2 x = *reinterpret_cast<const float2*>(&pr_w[2 * kp]);
            float4 m = Uh4[kp * 32 + l];
            hA.x = fmaf(m.x, x.x, hA.x); hA.y = fmaf(m.y, x.x, hA.y);
            hB.x = fmaf(m.z, x.y, hB.x); hB.y = fmaf(m.w, x.y, hB.y);
        }
        float2 h2;
        h2.x = z2.x * p2.x + (1.f - z2.x) * tanhf(hA.x + hB.x);
        h2.y = z2.y * p2.y + (1.f - z2.y) * tanhf(hA.y + hB.y);

        __stcg(reinterpret_cast<float2*>(g_h + (size_t)i * HD) + l, h2);
        if (i >= np1) {
            lm.x = fmaxf(lm.x, h2.x);
            lm.y = fmaxf(lm.y, h2.y);
        }
        __threadfence();          // release h stores
        __syncwarp();
        if (l == 0) g_ready[i] = 1;

        // ---- finish remaining gather for next step (pipelined cp.async path) ----
        if (has_next && pr_r0 < L)
            gather_pipelined(xwrN, xirN, pr_r0, L, xwS, xiS, xwS_a, xiS_a,
                             rl, rg, l, acc);
    }

    // fold local max, then last block writes output
    unsigned ux = __float_as_uint(lm.x);
    ux = (ux & 0x80000000u) ? ~ux : (ux | 0x80000000u);
    unsigned uy = __float_as_uint(lm.y);
    uy = (uy & 0x80000000u) ? ~uy : (uy | 0x80000000u);
    atomicMax(&g_max[2 * l], ux);
    atomicMax(&g_max[2 * l + 1], uy);
    __threadfence();
    __syncthreads();
    __shared__ unsigned s_last;
    if (tid == 0) s_last = (atomicAdd(&g_done, 1u) == BLKS - 1) ? 1u : 0u;
    __syncthreads();
    if (s_last && tid < HD) {
        unsigned u = atomicMax(&g_max[tid], 0u);   // atomic read of final value
        unsigned b = (u & 0x80000000u) ? (u & 0x7fffffffu) : ~u;
        out[tid] = __uint_as_float(b);
    }
}

// ---------------- launch ----------------
extern "C" void kernel_launch(void* const* d_in, const int* in_sizes, int n_in,
                              void* d_out, int out_size) {
    const float* xw = (const float*)d_in[0];
    const int* xi = (const int*)d_in[1];
    const int* tree = (const int*)d_in[2];
    const int* np = (const int*)d_in[3];
    const float* emb = (const float*)d_in[4];
    const float* Wz = (const float*)d_in[5];
    const float* Uz = (const float*)d_in[6];
    const float* bz = (const float*)d_in[7];
    const float* Wr = (const float*)d_in[8];
    const float* Ur = (const float*)d_in[9];
    const float* br = (const float*)d_in[10];
    const float* Wh = (const float*)d_in[11];
    const float* Uh = (const float*)d_in[12];
    const float* bh = (const float*)d_in[13];

    int N = in_sizes[2] / 2;      // tree is [N,2]
    int L = in_sizes[0] / N;      // x_word is [N,L]
    int n_steps = N - 1;
    int emb_total = in_sizes[4];  // V*H floats

    static int smem_set = 0;
    const int SMEM_BYTES = 28160 * 4;   // 112640: weights 96K + warp bufs + cp.async stage
    if (!smem_set) {
        cudaFuncSetAttribute(fused_kernel,
                             cudaFuncAttributeMaxDynamicSharedMemorySize, SMEM_BYTES);
        smem_set = 1;
    }

    int prep_threads = (emb_total + 7) / 8;
    if (prep_threads < MAXN) prep_threads = MAXN;
    prep_kernel<<<(prep_threads + 255) / 256, 256>>>(emb, tree, n_steps, emb_total);
    fill_kernel<<<(n_steps + 255) / 256, 256>>>(tree, n_steps);
    fused_kernel<<<BLKS, 256, SMEM_BYTES>>>(xw, xi, tree, Wz, Uz, bz, Wr, Ur, br,
                                            Wh, Uh, bh, np, L, n_steps,
                                            (float*)d_out);
}